// round 9
// baseline (speedup 1.0000x reference)
#include <cuda_runtime.h>
#include <cuda_bf16.h>
#include <cstdint>

// ---------------------------------------------------------------------------
// Problem constants
// ---------------------------------------------------------------------------
#define N_NODES 50000
#define N_EDGES 800000
#define IN_CH   128
#define MID_CH  256

// ---------------------------------------------------------------------------
// Scratch (device globals; no dynamic allocation allowed)
// ---------------------------------------------------------------------------
__device__ __align__(16) float g_deg[N_NODES];
__device__ __align__(16) float g_dis[N_NODES];
__device__ __align__(16) float g_h  [(size_t)N_NODES * IN_CH];
__device__ __align__(16) float g_agg[(size_t)N_NODES * IN_CH];
__device__ __align__(16) float g_h1 [(size_t)N_NODES * MID_CH];

// ---------------------------------------------------------------------------
// Degree / norm kernels
// ---------------------------------------------------------------------------
__global__ void k_deg_init()
{
    int i = blockIdx.x * blockDim.x + threadIdx.x;
    if (i < N_NODES) g_deg[i] = 1.0f;
}

__global__ void k_deg_count(const int* __restrict__ dst)
{
    int e = blockIdx.x * blockDim.x + threadIdx.x;
    if (e < N_EDGES) atomicAdd(&g_deg[dst[e]], 1.0f);
}

__global__ void k_dis()
{
    int i = blockIdx.x * blockDim.x + threadIdx.x;
    if (i < N_NODES) g_dis[i] = rsqrtf(g_deg[i]);
}

__global__ void k_out_init(float* __restrict__ out, const float* __restrict__ b3)
{
    int i = blockIdx.x * blockDim.x + threadIdx.x;
    if (i < N_NODES) out[i] = b3[0];
}

// ---------------------------------------------------------------------------
// TF32 tensor-core GEMM, cp.async tile double-buffer + register fragment
// double-buffer (prefetch kk+8 fragments before issuing kk MMAs).
// BM=BN=128, BK=32, 256 threads = 8 warps (2 x 4), warp tile 64x32.
// EPI: 0 = store(+bias/relu), 1 = conv (h AND agg=dis^2*h), 2 = fused W3 dot.
// ---------------------------------------------------------------------------
#define BM 128
#define BN 128
#define BK 32
#define APAD 4
#define BPAD 8

#define AS_STRIDE (BK + APAD)
#define BS_STRIDE (BN + BPAD)
#define AS_ELEMS  (BM * AS_STRIDE)
#define BS_ELEMS  (BK * BS_STRIDE)
#define GEMM_SMEM_BYTES ((2 * AS_ELEMS + 2 * BS_ELEMS) * 4)   // 71680

__device__ __forceinline__ uint32_t tf32r(float x)
{
    uint32_t u;
    asm("cvt.rna.tf32.f32 %0, %1;" : "=r"(u) : "f"(x));
    return u;
}

__device__ __forceinline__ void cp_async16(float* smem_dst, const float* gsrc, bool pred)
{
    uint32_t saddr = (uint32_t)__cvta_generic_to_shared(smem_dst);
    int sz = pred ? 16 : 0;
    asm volatile("cp.async.cg.shared.global [%0], [%1], 16, %2;"
                 :: "r"(saddr), "l"(gsrc), "r"(sz));
}

// Fragment load: 16 A scalars + 8 B scalars, converted to tf32.
#define LOAD_FRAGS(KKC, AF, BF)                                              \
    do {                                                                     \
        _Pragma("unroll")                                                    \
        for (int mt = 0; mt < 4; mt++) {                                     \
            int rb = warp_m * 64 + mt * 16;                                  \
            AF[mt][0] = tf32r(Ab[(rb + g    ) * AS_STRIDE + (KKC) + t    ]); \
            AF[mt][1] = tf32r(Ab[(rb + g + 8) * AS_STRIDE + (KKC) + t    ]); \
            AF[mt][2] = tf32r(Ab[(rb + g    ) * AS_STRIDE + (KKC) + t + 4]); \
            AF[mt][3] = tf32r(Ab[(rb + g + 8) * AS_STRIDE + (KKC) + t + 4]); \
        }                                                                    \
        _Pragma("unroll")                                                    \
        for (int nt = 0; nt < 4; nt++) {                                     \
            int cb = warp_n * 32 + nt * 8 + g;                               \
            BF[nt][0] = tf32r(Bb[((KKC) + t    ) * BS_STRIDE + cb]);         \
            BF[nt][1] = tf32r(Bb[((KKC) + t + 4) * BS_STRIDE + cb]);         \
        }                                                                    \
    } while (0)

#define MMA_STEP(AF, BF)                                                     \
    do {                                                                     \
        _Pragma("unroll")                                                    \
        for (int mt = 0; mt < 4; mt++)                                       \
            _Pragma("unroll")                                                \
            for (int nt = 0; nt < 4; nt++) {                                 \
                asm volatile(                                                \
                    "mma.sync.aligned.m16n8k8.row.col.f32.tf32.tf32.f32 "    \
                    "{%0,%1,%2,%3}, {%4,%5,%6,%7}, {%8,%9}, {%0,%1,%2,%3};"  \
                    : "+f"(acc[mt][nt][0]), "+f"(acc[mt][nt][1]),            \
                      "+f"(acc[mt][nt][2]), "+f"(acc[mt][nt][3])             \
                    : "r"(AF[mt][0]), "r"(AF[mt][1]),                        \
                      "r"(AF[mt][2]), "r"(AF[mt][3]),                        \
                      "r"(BF[nt][0]), "r"(BF[nt][1]));                       \
            }                                                                \
    } while (0)

template<int N, int K, int EPI, bool RELU, bool BIAS>
__device__ __forceinline__
void gemm_body(const float* __restrict__ A, const float* __restrict__ B,
               const float* __restrict__ bias, float* __restrict__ C,
               const float* __restrict__ W3, float* __restrict__ out, int M)
{
    extern __shared__ float smem[];
    float* As = smem;                          // [2][BM][AS_STRIDE]
    float* Bs = smem + 2 * AS_ELEMS;           // [2][BK][BS_STRIDE]

    const int tid  = threadIdx.x;
    const int wid  = tid >> 5;
    const int lane = tid & 31;
    const int g    = lane >> 2;
    const int t    = lane & 3;

    const int warp_m = wid & 1;
    const int warp_n = wid >> 1;

    const int row0 = blockIdx.y * BM;
    const int col0 = blockIdx.x * BN;

    float acc[4][4][4];
#pragma unroll
    for (int i = 0; i < 4; i++)
#pragma unroll
        for (int j = 0; j < 4; j++)
#pragma unroll
            for (int r = 0; r < 4; r++) acc[i][j][r] = 0.0f;

    const int NT = K / BK;

    // ---- prefetch tile 0 via cp.async ----
    {
        float* Abuf = As;
        float* Bbuf = Bs;
#pragma unroll
        for (int it = 0; it < 4; it++) {
            int idx = tid + it * 256;
            int r = idx >> 3, c4 = idx & 7;
            int gr = row0 + r;
            const float* src = A + (size_t)(gr < M ? gr : 0) * K + c4 * 4;
            cp_async16(&Abuf[r * AS_STRIDE + c4 * 4], src, gr < M);
        }
#pragma unroll
        for (int it = 0; it < 4; it++) {
            int idx = tid + it * 256;
            int r = idx >> 5, c4 = idx & 31;
            cp_async16(&Bbuf[r * BS_STRIDE + c4 * 4],
                       B + (size_t)r * N + col0 + c4 * 4, true);
        }
        asm volatile("cp.async.commit_group;");
    }

#pragma unroll 1
    for (int kt = 0; kt < NT; kt++) {
        asm volatile("cp.async.wait_group 0;");
        __syncthreads();

        // prefetch next tile into other buffer
        if (kt + 1 < NT) {
            int k0 = (kt + 1) * BK;
            float* Abuf = As + ((kt + 1) & 1) * AS_ELEMS;
            float* Bbuf = Bs + ((kt + 1) & 1) * BS_ELEMS;
#pragma unroll
            for (int it = 0; it < 4; it++) {
                int idx = tid + it * 256;
                int r = idx >> 3, c4 = idx & 7;
                int gr = row0 + r;
                const float* src = A + (size_t)(gr < M ? gr : 0) * K + k0 + c4 * 4;
                cp_async16(&Abuf[r * AS_STRIDE + c4 * 4], src, gr < M);
            }
#pragma unroll
            for (int it = 0; it < 4; it++) {
                int idx = tid + it * 256;
                int r = idx >> 5, c4 = idx & 31;
                cp_async16(&Bbuf[r * BS_STRIDE + c4 * 4],
                           B + (size_t)(k0 + r) * N + col0 + c4 * 4, true);
            }
            asm volatile("cp.async.commit_group;");
        }

        const float* Ab = As + (kt & 1) * AS_ELEMS;
        const float* Bb = Bs + (kt & 1) * BS_ELEMS;

        // ---- fragment-level software pipeline over kk-steps ----
        uint32_t af0[4][4], bf0[4][2];
        uint32_t af1[4][4], bf1[4][2];

        LOAD_FRAGS(0, af0, bf0);          // prefetch kk=0
        LOAD_FRAGS(8, af1, bf1);          // prefetch kk=8
        MMA_STEP(af0, bf0);               // kk=0
        LOAD_FRAGS(16, af0, bf0);         // prefetch kk=16
        MMA_STEP(af1, bf1);               // kk=8
        LOAD_FRAGS(24, af1, bf1);         // prefetch kk=24
        MMA_STEP(af0, bf0);               // kk=16
        MMA_STEP(af1, bf1);               // kk=24

        __syncthreads();
    }

    // ---- epilogue ----
#pragma unroll
    for (int mt = 0; mt < 4; mt++) {
#pragma unroll
        for (int half = 0; half < 2; half++) {
            int gr = row0 + warp_m * 64 + mt * 16 + g + half * 8;
            if (gr >= M) continue;

            if (EPI == 2) {
                float s = 0.0f;
#pragma unroll
                for (int nt = 0; nt < 4; nt++) {
                    int gc = col0 + warp_n * 32 + nt * 8 + t * 2;
                    float v0 = acc[mt][nt][half * 2 + 0] + bias[gc];
                    float v1 = acc[mt][nt][half * 2 + 1] + bias[gc + 1];
                    v0 = fmaxf(v0, 0.0f);
                    v1 = fmaxf(v1, 0.0f);
                    s = fmaf(v0, __ldg(W3 + gc), s);
                    s = fmaf(v1, __ldg(W3 + gc + 1), s);
                }
                atomicAdd(out + gr, s);
            } else if (EPI == 1) {
                float dsq = g_dis[gr];
                dsq = dsq * dsq;
#pragma unroll
                for (int nt = 0; nt < 4; nt++) {
                    int gc = col0 + warp_n * 32 + nt * 8 + t * 2;
                    float v0 = acc[mt][nt][half * 2 + 0];
                    float v1 = acc[mt][nt][half * 2 + 1];
                    *reinterpret_cast<float2*>(C + (size_t)gr * N + gc) =
                        make_float2(v0, v1);
                    *reinterpret_cast<float2*>(g_agg + (size_t)gr * N + gc) =
                        make_float2(dsq * v0, dsq * v1);
                }
            } else {
#pragma unroll
                for (int nt = 0; nt < 4; nt++) {
                    int gc = col0 + warp_n * 32 + nt * 8 + t * 2;
                    float v0 = acc[mt][nt][half * 2 + 0];
                    float v1 = acc[mt][nt][half * 2 + 1];
                    if (BIAS) { v0 += bias[gc]; v1 += bias[gc + 1]; }
                    if (RELU) { v0 = fmaxf(v0, 0.0f); v1 = fmaxf(v1, 0.0f); }
                    *reinterpret_cast<float2*>(C + (size_t)gr * N + gc) =
                        make_float2(v0, v1);
                }
            }
        }
    }
}

__global__ __launch_bounds__(256, 2)
void k_gemm_conv(const float* __restrict__ x, const float* __restrict__ W)
{
    gemm_body<IN_CH, IN_CH, 1, false, false>(x, W, nullptr, g_h, nullptr, nullptr, N_NODES);
}

__global__ __launch_bounds__(256, 2)
void k_gemm_mlp1(const float* __restrict__ W1, const float* __restrict__ b1)
{
    gemm_body<MID_CH, IN_CH, 0, true, true>(g_h, W1, b1, g_h1, nullptr, nullptr, N_NODES);
}

__global__ __launch_bounds__(256, 2)
void k_gemm_mlp2(const float* __restrict__ W2, const float* __restrict__ b2,
                 const float* __restrict__ W3, float* __restrict__ out)
{
    gemm_body<MID_CH, MID_CH, 2, true, true>(g_h1, W2, b2, nullptr, W3, out, N_NODES);
}

// ---------------------------------------------------------------------------
// Edge scatter: agg[dst,:] += dis[src]*dis[dst] * h[src,:]
// One warp per edge, lane = 4 channels, vector RED.
// ---------------------------------------------------------------------------
__global__ __launch_bounds__(256)
void k_scatter(const int* __restrict__ src, const int* __restrict__ dst)
{
    int e = blockIdx.x * 8 + (threadIdx.x >> 5);
    if (e >= N_EDGES) return;
    int lane = threadIdx.x & 31;

    int s = __ldg(src + e);
    int d = __ldg(dst + e);
    float nrm = g_dis[s] * g_dis[d];

    float4 v = reinterpret_cast<const float4*>(g_h + (size_t)s * IN_CH)[lane];
    v.x *= nrm; v.y *= nrm; v.z *= nrm; v.w *= nrm;

    float* ag = g_agg + (size_t)d * IN_CH + lane * 4;
    asm volatile("red.global.add.v4.f32 [%0], {%1, %2, %3, %4};"
                 :: "l"(ag), "f"(v.x), "f"(v.y), "f"(v.z), "f"(v.w)
                 : "memory");
}

// ---------------------------------------------------------------------------
// Post-conv epilogue: h = relu(agg + b_conv) + x
// ---------------------------------------------------------------------------
__global__ void k_postconv(const float* __restrict__ x, const float* __restrict__ b_conv)
{
    size_t i = (size_t)blockIdx.x * blockDim.x + threadIdx.x;   // float4 index
    if (i >= (size_t)N_NODES * IN_CH / 4) return;
    int c4 = (int)(i & 31);
    float4 b  = reinterpret_cast<const float4*>(b_conv)[c4];
    float4 a  = reinterpret_cast<const float4*>(g_agg)[i];
    float4 xr = reinterpret_cast<const float4*>(x)[i];
    float4 o;
    o.x = fmaxf(a.x + b.x, 0.0f) + xr.x;
    o.y = fmaxf(a.y + b.y, 0.0f) + xr.y;
    o.z = fmaxf(a.z + b.z, 0.0f) + xr.z;
    o.w = fmaxf(a.w + b.w, 0.0f) + xr.w;
    reinterpret_cast<float4*>(g_h)[i] = o;
}

// ---------------------------------------------------------------------------
// kernel_launch
// ---------------------------------------------------------------------------
extern "C" void kernel_launch(void* const* d_in, const int* in_sizes, int n_in,
                              void* d_out, int out_size)
{
    const float* x      = (const float*)d_in[0];
    const int*   eidx   = (const int*)d_in[1];     // int32 (JAX x64 disabled)
    const float* W_conv = (const float*)d_in[2];
    const float* b_conv = (const float*)d_in[3];
    const float* W1     = (const float*)d_in[4];
    const float* b1     = (const float*)d_in[5];
    const float* W2     = (const float*)d_in[6];
    const float* b2     = (const float*)d_in[7];
    const float* W3     = (const float*)d_in[8];
    const float* b3     = (const float*)d_in[9];
    float*       out    = (float*)d_out;

    const int* e_src = eidx;
    const int* e_dst = eidx + N_EDGES;

    cudaFuncSetAttribute(k_gemm_conv, cudaFuncAttributeMaxDynamicSharedMemorySize, GEMM_SMEM_BYTES);
    cudaFuncSetAttribute(k_gemm_mlp1, cudaFuncAttributeMaxDynamicSharedMemorySize, GEMM_SMEM_BYTES);
    cudaFuncSetAttribute(k_gemm_mlp2, cudaFuncAttributeMaxDynamicSharedMemorySize, GEMM_SMEM_BYTES);

    k_deg_init<<<(N_NODES + 255) / 256, 256>>>();
    k_deg_count<<<(N_EDGES + 255) / 256, 256>>>(e_dst);
    k_dis<<<(N_NODES + 255) / 256, 256>>>();

    // h = x @ W_conv ; agg = dis^2 * h
    {
        dim3 grid(IN_CH / BN, (N_NODES + BM - 1) / BM);
        k_gemm_conv<<<grid, 256, GEMM_SMEM_BYTES>>>(x, W_conv);
    }

    // edge scatter into agg
    k_scatter<<<(N_EDGES + 7) / 8, 256>>>(e_src, e_dst);

    // h = relu(agg + b_conv) + x
    {
        size_t tot4 = (size_t)N_NODES * IN_CH / 4;
        k_postconv<<<(unsigned)((tot4 + 255) / 256), 256>>>(x, b_conv);
    }

    // h1 = relu(h @ W1 + b1)
    {
        dim3 grid(MID_CH / BN, (N_NODES + BM - 1) / BM);
        k_gemm_mlp1<<<grid, 256, GEMM_SMEM_BYTES>>>(W1, b1);
    }

    // out = relu(h1 @ W2 + b2) @ W3 + b3
    k_out_init<<<(N_NODES + 255) / 256, 256>>>(out, b3);
    {
        dim3 grid(MID_CH / BN, (N_NODES + BM - 1) / BM);
        k_gemm_mlp2<<<grid, 256, GEMM_SMEM_BYTES>>>(W2, b2, W3, out);
    }
}